// round 17
// baseline (speedup 1.0000x reference)
#include <cuda_runtime.h>
#include <cuda_bf16.h>
#include <cstdint>

// out = sum_i | cumsum(x0 - x1)_i |, x = d_in[0] as (2, N) fp32, N = 2^23.
// 148 resident blocks x 1024 thr; each block processes chunks {b, b+148} of
// 7168 float4. Prefixes live in REGISTERS (7 float4/thread) — no smem payload,
// no global barrier. Per chunk: fused load->tile-scan -> publish {gen,agg} ->
// decoupled lookback over preceding chunks -> abs over register prefixes.
// Done-counter finisher reduces 293 chunk partials (fp64), resets generation.

#define GRID_N   148
#define NCHUNK   293              // ceil(2097152 / 7168)
#define TPB      1024
#define NWARP    32
#define BLK_F4   7168             // float4 per chunk
#define WARP_F4  224
#define LANE_J   7                // tiles per warp per chunk

typedef unsigned long long ull;

__device__ ull      g_pub[NCHUNK];     // {gen_tag:32 | fp32 chunk aggregate:32}
__device__ float    g_partials[NCHUNK];
__device__ unsigned g_done;            // zero-init; reset by finisher
__device__ unsigned g_gen = 1;

__global__ void __launch_bounds__(TPB, 1) emd_scan(const float* __restrict__ x,
                                                   float* __restrict__ out, int N) {
    __shared__ float    sWarpSums[NWARP];
    __shared__ float    sWarpAcc[NWARP];
    __shared__ float    sChunkPrefix;
    __shared__ unsigned sGen;
    __shared__ unsigned sLast;

    const int  tid  = threadIdx.x;
    const int  w    = tid >> 5;
    const int  lane = tid & 31;
    const int  bid  = blockIdx.x;
    const long tot4 = (long)N / 4;     // 2097152

    if (tid == 0) { sGen = *(volatile unsigned*)&g_gen; sLast = 0u; }
    __syncthreads();
    const unsigned gen = sGen;

    const float4* x0 = (const float4*)x;
    const float4* x1 = (const float4*)(x + N);
    const float4  z4 = make_float4(0.f, 0.f, 0.f, 0.f);

    // up to 2 chunks per block: c = bid, bid + GRID_N
    for (int c = bid; c < NCHUNK; c += GRID_N) {
        const long chunkStart4 = (long)c * BLK_F4;
        const int  warpLocal4  = w * WARP_F4;
        const long base4       = chunkStart4 + warpLocal4 + lane;

        // ---------- Phase A: fused load -> tile scans, prefixes in regs ----------
        float4 d[LANE_J];              // warp-relative inclusive prefixes
        float  carry = 0.f;

        float4 a = (base4 < tot4) ? x0[base4] : z4;
        float4 b = (base4 < tot4) ? x1[base4] : z4;

#pragma unroll
        for (int j = 0; j < LANE_J; ++j) {
            float4 an = z4, bn = z4;
            if (j + 1 < LANE_J) {
                long n4 = base4 + (j + 1) * 32;
                if (n4 < tot4) { an = x0[n4]; bn = x1[n4]; }
            }

            float s0 = a.x - b.x;
            float s1 = s0 + (a.y - b.y);
            float s2 = s1 + (a.z - b.z);
            float s3 = s2 + (a.w - b.w);

            float v = s3;              // warp inclusive scan of lane totals
#pragma unroll
            for (int off = 1; off < 32; off <<= 1) {
                float n = __shfl_up_sync(0xffffffffu, v, off);
                if (lane >= off) v += n;
            }
            float base = carry + (v - s3);
            d[j].x = base + s0; d[j].y = base + s1;
            d[j].z = base + s2; d[j].w = base + s3;
            carry += __shfl_sync(0xffffffffu, v, 31);

            a = an; b = bn;
        }
        if (lane == 0) sWarpSums[w] = carry;
        __syncthreads();

        // ---------- publish aggregate + lookback over preceding chunks ----------
        if (w == 0) {
            float agg = sWarpSums[lane];
#pragma unroll
            for (int off = 16; off; off >>= 1)
                agg += __shfl_down_sync(0xffffffffu, agg, off);
            if (lane == 0)
                atomicExch(&g_pub[c], ((ull)gen << 32) | (ull)__float_as_uint(agg));

            float p = 0.f;
            for (int j = lane; j < c; j += 32) {
                ull pk;
                do { pk = *(volatile ull*)&g_pub[j]; }
                while ((unsigned)(pk >> 32) != gen);
                p += __uint_as_float((unsigned)pk);
            }
#pragma unroll
            for (int off = 16; off; off >>= 1)
                p += __shfl_down_sync(0xffffffffu, p, off);
            if (lane == 0) sChunkPrefix = p;
        }
        __syncthreads();

        float warpBase = sChunkPrefix;
        for (int i = 0; i < w; ++i) warpBase += sWarpSums[i];

        // ---------- abs over register prefixes ----------
        float a0 = 0.f, a1 = 0.f, a2 = 0.f, a3 = 0.f;
#pragma unroll
        for (int j = 0; j < LANE_J; ++j) {
            if (base4 + j * 32 < tot4) {
                a0 += fabsf(warpBase + d[j].x);
                a1 += fabsf(warpBase + d[j].y);
                a2 += fabsf(warpBase + d[j].z);
                a3 += fabsf(warpBase + d[j].w);
            }
        }
        float acc = (a0 + a1) + (a2 + a3);
#pragma unroll
        for (int off = 16; off; off >>= 1)
            acc += __shfl_down_sync(0xffffffffu, acc, off);
        if (lane == 0) sWarpAcc[w] = acc;
        __syncthreads();

        if (tid == 0) {
            float bp = 0.f;
#pragma unroll
            for (int i = 0; i < NWARP; ++i) bp += sWarpAcc[i];
            atomicExch(&g_partials[c], bp);
            __threadfence();
            unsigned old = atomicAdd(&g_done, 1u);
            if (old == NCHUNK - 1) sLast = 1u;
        }
        __syncthreads();
    }

    // ---------- finisher: reduce 293 chunk partials (fp64) ----------
    if (sLast && w == 0) {
        double p = 0.0;
        for (int i = lane; i < NCHUNK; i += 32)
            p += (double)(*(volatile float*)&g_partials[i]);
#pragma unroll
        for (int off = 16; off; off >>= 1)
            p += __shfl_down_sync(0xffffffffu, p, off);
        if (lane == 0) {
            out[0] = (float)p;
            *(volatile unsigned*)&g_done = 0;        // reset for next replay
            __threadfence();
            *(volatile unsigned*)&g_gen = gen + 1;   // invalidate g_pub tags
        }
    }
}

extern "C" void kernel_launch(void* const* d_in, const int* in_sizes, int n_in,
                              void* d_out, int out_size) {
    const float* x = (const float*)d_in[0];
    int N = in_sizes[0] / 2;               // 8388608
    emd_scan<<<GRID_N, TPB>>>(x, (float*)d_out, N);
}